// round 17
// baseline (speedup 1.0000x reference)
#include <cuda_runtime.h>
#include <cuda_fp16.h>
#include <math.h>
#include <stdint.h>

// ---------------- scratch (no allocation allowed) ----------------
__device__ __half g_hs[6400000];   // 50000 x 128 halves (256B-aligned rows)
__device__ __half g_x1[6400000];   // layer-1 input, fp16, 128-stride padded
__device__ float  g_dinv[50048];
__device__ int    g_cnt[50048];    // statically zero; re-zeroed by csr_build each call
__device__ int    g_rowptr[50049];
__device__ int    g_off[50049];
__device__ int    g_adj[800064];
__device__ int    g_bsum[256];
__device__ float  g_partials[512];
__device__ float  g_norm2;
__device__ unsigned g_barcnt = 0;
__device__ unsigned g_bargen = 0;

// ---------------- ||x||^2 partial sums ----------------
__global__ void sumsq_kernel(const float* __restrict__ x, long n) {
    int gs = gridDim.x * blockDim.x;
    float s = 0.f;
    for (long i = (long)blockIdx.x * blockDim.x + threadIdx.x; i < n; i += gs) {
        float v = x[i];
        s += v * v;
    }
    __shared__ float sm[256];
    sm[threadIdx.x] = s;
    __syncthreads();
    for (int o = 128; o > 0; o >>= 1) {
        if (threadIdx.x < o) sm[threadIdx.x] += sm[threadIdx.x + o];
        __syncthreads();
    }
    if (threadIdx.x == 0) g_partials[blockIdx.x] = sm[0];
}

__global__ void normfin_kernel() {
    __shared__ float fm[256];
    fm[threadIdx.x] = g_partials[threadIdx.x] + g_partials[threadIdx.x + 256];
    __syncthreads();
    for (int o = 128; o > 0; o >>= 1) {
        if (threadIdx.x < o) fm[threadIdx.x] += fm[threadIdx.x + o];
        __syncthreads();
    }
    if (threadIdx.x == 0) g_norm2 = fm[0];
}

// ---------------- fused CSR build: hist + scan + dinv + fill (1 kernel) ----------------
#define CSR_NB 196

__device__ __forceinline__ void gridbar() {
    __syncthreads();
    if (threadIdx.x == 0) {
        unsigned gen = atomicAdd(&g_bargen, 0u);
        __threadfence();
        unsigned t = atomicAdd(&g_barcnt, 1u);
        if (t == CSR_NB - 1) {
            g_barcnt = 0;
            __threadfence();
            atomicAdd(&g_bargen, 1u);
        } else {
            while (atomicAdd(&g_bargen, 0u) == gen) {}
        }
        __threadfence();
    }
    __syncthreads();
}

__global__ void __launch_bounds__(256)
csr_build_kernel(const int* __restrict__ src, const int* __restrict__ dst,
                 int N, int E) {
    int tid = threadIdx.x;
    int gtid = blockIdx.x * 256 + tid;
    const int gs = CSR_NB * 256;

    // P1: degree histogram (fire-and-forget REDs)
    for (int i = gtid; i < E; i += gs) atomicAdd(&g_cnt[dst[i]], 1);
    gridbar();

    // P2: per-block scan of 256 counts + dinv
    __shared__ int sm[256];
    int node = gtid;
    int c = (node < N) ? g_cnt[node] : 0;
    if (node < N) g_dinv[node] = rsqrtf((float)(c + 1));  // +1 self-loop
    sm[tid] = c;
    __syncthreads();
    for (int o = 1; o < 256; o <<= 1) {
        int v = (tid >= o) ? sm[tid - o] : 0;
        __syncthreads();
        sm[tid] += v;
        __syncthreads();
    }
    int local_excl = sm[tid] - c;
    if (tid == 255) g_bsum[blockIdx.x] = sm[255];
    gridbar();

    // P3: block 0 scans the 196 block sums
    if (blockIdx.x == 0) {
        int b = (tid < CSR_NB) ? g_bsum[tid] : 0;
        sm[tid] = b;
        __syncthreads();
        for (int o = 1; o < 256; o <<= 1) {
            int v = (tid >= o) ? sm[tid - o] : 0;
            __syncthreads();
            sm[tid] += v;
            __syncthreads();
        }
        if (tid < CSR_NB) g_bsum[tid] = sm[tid] - b;  // exclusive
    }
    gridbar();

    // P4: finalize rowptr/off; re-zero cnt for next replay
    int boff = g_bsum[blockIdx.x];
    if (node < N) {
        int r = local_excl + boff;
        g_rowptr[node] = r;
        g_off[node] = r;
        g_cnt[node] = 0;
    } else if (node == N) {
        g_rowptr[N] = E;
    }
    gridbar();

    // P5: fill adjacency
    for (int i = gtid; i < E; i += gs) {
        int pos = atomicAdd(&g_off[dst[i]], 1);
        g_adj[pos] = src[i];
    }
}

// ---------------- fp16 tensor-core GEMM ----------------
// HALF_IN: 0 = fp32 X stride 100, 1 = fp16 X stride 128 (pre-padded)
// USE_DINV: scale output rows by g_dinv[row]
#define SX_STRIDE 120
template<int HALF_IN, int USE_DINV>
__global__ void __launch_bounds__(256, 3)
gemm_mma_kernel(const void* __restrict__ Xv, const float* __restrict__ W,
                __half* __restrict__ hs, int N) {
    extern __shared__ __half smem_h[];
    __half* sX = smem_h;                    // 128 x 120
    __half* sWt = smem_h + 128 * SX_STRIDE; // 104 x 120
    int tid = threadIdx.x;
    int row0 = blockIdx.x * 128;
    const uint2 z2 = make_uint2(0u, 0u);

    for (int i = tid; i < 104 * SX_STRIDE / 4; i += 256)
        ((uint2*)sWt)[i] = z2;

    {
        int r = tid >> 1, h = tid & 1;
        int gr = row0 + r;
        __half* drow = sX + r * SX_STRIDE;
        if (gr < N) {
            if (HALF_IN) {
                const uint2* srcp = (const uint2*)((const __half*)Xv + (size_t)gr * 128);
#pragma unroll
                for (int t = 0; t < 13; t++) {
                    int c4 = h * 13 + t;
                    if (c4 < 25) *(uint2*)(drow + c4 * 4) = __ldg(srcp + c4);
                }
            } else {
                const float4* srcp = (const float4*)((const float*)Xv + (size_t)gr * 100);
#pragma unroll
                for (int t = 0; t < 13; t++) {
                    int c4 = h * 13 + t;
                    if (c4 < 25) {
                        float4 v = __ldg(srcp + c4);
                        __half2 lo = __floats2half2_rn(v.x, v.y);
                        __half2 hi = __floats2half2_rn(v.z, v.w);
                        uint2 u;
                        u.x = *(uint32_t*)&lo; u.y = *(uint32_t*)&hi;
                        *(uint2*)(drow + c4 * 4) = u;
                    }
                }
            }
        } else {
#pragma unroll
            for (int t = 0; t < 13; t++) {
                int c4 = h * 13 + t;
                if (c4 < 25) *(uint2*)(drow + c4 * 4) = z2;
            }
        }
        if (h) {
            *(uint2*)(drow + 100) = z2;
            *(uint2*)(drow + 104) = z2;
            *(uint2*)(drow + 108) = z2;
        }
    }
    __syncthreads();

    for (int i = tid; i < 10000; i += 256) {
        int k = i / 100, n = i - k * 100;
        sWt[n * SX_STRIDE + k] = __float2half_rn(__ldg(W + i));
    }
    __syncthreads();

    int warp = tid >> 5, lane = tid & 31;
    int grp = lane >> 2, tig = lane & 3;
    const __half* xw0 = sX + (warp * 16 + grp) * SX_STRIDE;
    const __half* xw1 = xw0 + 8 * SX_STRIDE;

    float acc[13][4];
#pragma unroll
    for (int nt = 0; nt < 13; nt++)
#pragma unroll
        for (int i = 0; i < 4; i++) acc[nt][i] = 0.f;

#pragma unroll
    for (int kc = 0; kc < 7; kc++) {
        int k0 = kc * 16;
        uint32_t a0 = *(const uint32_t*)(xw0 + k0 + 2 * tig);
        uint32_t a1 = *(const uint32_t*)(xw1 + k0 + 2 * tig);
        uint32_t a2 = *(const uint32_t*)(xw0 + k0 + 2 * tig + 8);
        uint32_t a3 = *(const uint32_t*)(xw1 + k0 + 2 * tig + 8);
        const __half* wb = sWt + grp * SX_STRIDE + k0 + 2 * tig;
#pragma unroll
        for (int nt = 0; nt < 13; nt++) {
            uint32_t b0 = *(const uint32_t*)(wb + nt * 8 * SX_STRIDE);
            uint32_t b1 = *(const uint32_t*)(wb + nt * 8 * SX_STRIDE + 8);
            asm volatile(
                "mma.sync.aligned.m16n8k16.row.col.f32.f16.f16.f32 "
                "{%0,%1,%2,%3}, {%4,%5,%6,%7}, {%8,%9}, {%0,%1,%2,%3};"
                : "+f"(acc[nt][0]), "+f"(acc[nt][1]), "+f"(acc[nt][2]), "+f"(acc[nt][3])
                : "r"(a0), "r"(a1), "r"(a2), "r"(a3), "r"(b0), "r"(b1));
        }
    }

    int gr0 = row0 + warp * 16 + grp;
    int gr1 = gr0 + 8;
    float s0 = (gr0 < N) ? (USE_DINV ? g_dinv[gr0] : 1.0f) : 0.f;
    float s1 = (gr1 < N) ? (USE_DINV ? g_dinv[gr1] : 1.0f) : 0.f;
#pragma unroll
    for (int nt = 0; nt < 13; nt++) {
        int col = nt * 8 + 2 * tig;
        if (gr0 < N) {
            __half2 h = __floats2half2_rn(acc[nt][0] * s0, acc[nt][1] * s0);
            *(__half2*)(hs + (size_t)gr0 * 128 + col) = h;
        }
        if (gr1 < N) {
            __half2 h = __floats2half2_rn(acc[nt][2] * s1, acc[nt][3] * s1);
            *(__half2*)(hs + (size_t)gr1 * 128 + col) = h;
        }
    }
}

// ---------------- agg after layer0 (hs UNscaled; R7-style per-edge dinv) ----------------
// x1 = fp16( (dinv_i*rsqrt(norm2)) * (dinv_i*hs_i + sum_j dinv_j*hs_j) + cb0 )
__global__ void __launch_bounds__(256)
agg_kernel(const __half* __restrict__ hs, __half* __restrict__ x1,
           const int* __restrict__ rowptr, const int* __restrict__ adj,
           const float* __restrict__ cb, int N) {
    int node = (blockIdx.x * 256 + threadIdx.x) >> 5;
    int lane = threadIdx.x & 31;
    if (node >= N) return;
    bool act = lane < 25;
    float di = g_dinv[node];

    float4 sum = make_float4(0.f, 0.f, 0.f, 0.f);
    if (act) {
        uint2 raw = __ldg((const uint2*)(hs + (size_t)node * 128) + lane);
        float2 f0 = __half22float2(*(const __half2*)&raw.x);
        float2 f1 = __half22float2(*(const __half2*)&raw.y);
        sum.x = di * f0.x; sum.y = di * f0.y;
        sum.z = di * f1.x; sum.w = di * f1.y;
    }

    int beg = rowptr[node];
    int end = rowptr[node + 1];
    for (int base = beg; base < end; base += 32) {
        int idx = base + lane;
        int my = 0; float md = 0.f;
        if (idx < end) {
            my = __ldg(adj + idx);
            md = g_dinv[my];
        }
        int cnt = min(32, end - base);
#pragma unroll 8
        for (int j = 0; j < cnt; j++) {
            int s = __shfl_sync(0xffffffffu, my, j);
            float d = __shfl_sync(0xffffffffu, md, j);
            if (act) {
                uint2 raw = __ldg((const uint2*)(hs + (size_t)s * 128) + lane);
                float2 f0 = __half22float2(*(const __half2*)&raw.x);
                float2 f1 = __half22float2(*(const __half2*)&raw.y);
                sum.x += d * f0.x; sum.y += d * f0.y;
                sum.z += d * f1.x; sum.w += d * f1.y;
            }
        }
    }

    __half* xrow = x1 + (size_t)node * 128;
    if (act) {
        float os = di * rsqrtf(g_norm2);
        float4 b = __ldg((const float4*)cb + lane);
        __half2 lo = __floats2half2_rn(sum.x * os + b.x, sum.y * os + b.y);
        __half2 hi = __floats2half2_rn(sum.z * os + b.z, sum.w * os + b.w);
        uint2 u;
        u.x = *(uint32_t*)&lo; u.y = *(uint32_t*)&hi;
        *((uint2*)xrow + lane) = u;
    } else {
        *((uint2*)xrow + lane) = make_uint2(0u, 0u);
    }
}

// ---------------- fused agg after layer1 + MLP head  [R16-verbatim] ----------------
__global__ void __launch_bounds__(256)
agg_head_kernel(const __half* __restrict__ hs,
                const int* __restrict__ rowptr, const int* __restrict__ adj,
                const float* __restrict__ cb,
                const float* __restrict__ W0, const float* __restrict__ b0,
                const float* __restrict__ W1, const float* __restrict__ b1,
                float* __restrict__ out, int N) {
    __shared__ float w0t[10 * 104];
    __shared__ float b0s[10];
    __shared__ float w1s[10];
    __shared__ float b1v;
    int tid = threadIdx.x;

    for (int i = tid; i < 1000; i += 256) {
        int k = i / 10, j = i - k * 10;
        w0t[j * 104 + k] = __ldg(W0 + i);
    }
    if (tid < 10) { b0s[tid] = __ldg(b0 + tid); w1s[tid] = __ldg(W1 + tid); }
    if (tid == 0) b1v = __ldg(b1);
    __syncthreads();

    int node = (blockIdx.x * 256 + tid) >> 5;
    int lane = tid & 31;
    if (node >= N) return;
    bool act = lane < 25;

    float4 sum = make_float4(0.f, 0.f, 0.f, 0.f);
    if (act) {
        uint2 raw = __ldg((const uint2*)(hs + (size_t)node * 128) + lane);
        float2 f0 = __half22float2(*(const __half2*)&raw.x);
        float2 f1 = __half22float2(*(const __half2*)&raw.y);
        sum.x = f0.x; sum.y = f0.y; sum.z = f1.x; sum.w = f1.y;
    }
    int beg = rowptr[node];
    int end = rowptr[node + 1];
    for (int base = beg; base < end; base += 32) {
        int idx = base + lane;
        int my = (idx < end) ? __ldg(adj + idx) : 0;
        int cnt = min(32, end - base);
#pragma unroll 8
        for (int j = 0; j < cnt; j++) {
            int s = __shfl_sync(0xffffffffu, my, j);
            if (act) {
                uint2 raw = __ldg((const uint2*)(hs + (size_t)s * 128) + lane);
                float2 f0 = __half22float2(*(const __half2*)&raw.x);
                float2 f1 = __half22float2(*(const __half2*)&raw.y);
                sum.x += f0.x; sum.y += f0.y; sum.z += f1.x; sum.w += f1.y;
            }
        }
    }

    float4 x2 = make_float4(0.f, 0.f, 0.f, 0.f);
    if (act) {
        float di = g_dinv[node];
        float4 b = __ldg((const float4*)cb + lane);
        x2.x = di * sum.x + b.x; x2.y = di * sum.y + b.y;
        x2.z = di * sum.z + b.z; x2.w = di * sum.w + b.w;
    }

    float p[10];
#pragma unroll
    for (int j = 0; j < 10; j++) {
        float4 w = make_float4(0.f, 0.f, 0.f, 0.f);
        if (act) w = *(const float4*)(w0t + j * 104 + 4 * lane);
        p[j] = x2.x * w.x + x2.y * w.y + x2.z * w.z + x2.w * w.w;
    }
#pragma unroll
    for (int j = 0; j < 10; j++) {
#pragma unroll
        for (int off = 16; off > 0; off >>= 1)
            p[j] += __shfl_xor_sync(0xffffffffu, p[j], off);
    }
    if (lane == 0) {
        float o = b1v;
#pragma unroll
        for (int j = 0; j < 10; j++) o += fmaxf(p[j] + b0s[j], 0.f) * w1s[j];
        out[node] = o;
    }
}

extern "C" void kernel_launch(void* const* d_in, const int* in_sizes, int n_in,
                              void* d_out, int out_size) {
    const float* x   = (const float*)d_in[0];
    const int*   ei  = (const int*)d_in[1];
    const float* W0  = (const float*)d_in[2];
    const float* cb0 = (const float*)d_in[3];
    const float* W1  = (const float*)d_in[4];
    const float* cb1 = (const float*)d_in[5];
    const float* lW0 = (const float*)d_in[6];
    const float* lb0 = (const float*)d_in[7];
    const float* lW1 = (const float*)d_in[8];
    const float* lb1 = (const float*)d_in[9];
    float* out = (float*)d_out;

    int N = in_sizes[0] / 100;
    int E = in_sizes[1] / 2;
    const int* src = ei;
    const int* dst = ei + E;

    size_t gemm_smem = (128 + 104) * SX_STRIDE * sizeof(__half);  // 55.7 KB -> 3 blocks/SM
    cudaFuncSetAttribute(gemm_mma_kernel<0, 0>,
                         cudaFuncAttributeMaxDynamicSharedMemorySize, (int)gemm_smem);
    cudaFuncSetAttribute(gemm_mma_kernel<1, 1>,
                         cudaFuncAttributeMaxDynamicSharedMemorySize, (int)gemm_smem);

    __half *hs, *x1;
    int *rowptr, *adj;
    cudaGetSymbolAddress((void**)&hs, g_hs);
    cudaGetSymbolAddress((void**)&x1, g_x1);
    cudaGetSymbolAddress((void**)&rowptr, g_rowptr);
    cudaGetSymbolAddress((void**)&adj, g_adj);

    cudaStream_t s2;
    cudaStreamCreateWithFlags(&s2, cudaStreamNonBlocking);
    cudaEvent_t ev0, ev1;
    cudaEventCreateWithFlags(&ev0, cudaEventDisableTiming);
    cudaEventCreateWithFlags(&ev1, cudaEventDisableTiming);

    cudaEventRecord(ev0, 0);
    cudaStreamWaitEvent(s2, ev0, 0);

    // default: fused CSR build (hist + scan + dinv + fill), one launch
    csr_build_kernel<<<CSR_NB, 256>>>(src, dst, N, E);

    // s2 (fully parallel): gemm0 (pure X@W0), sumsq, norm finalize
    int gblocks = (N + 127) / 128;
    gemm_mma_kernel<0, 0><<<gblocks, 256, gemm_smem, s2>>>(x, W0, hs, N);
    long n_elem = (long)N * 100;
    sumsq_kernel<<<512, 256, 0, s2>>>(x, n_elem);
    normfin_kernel<<<1, 256, 0, s2>>>();
    cudaEventRecord(ev1, s2);

    cudaStreamWaitEvent(0, ev1, 0);  // join

    int ablocks = (N + 7) / 8;
    agg_kernel<<<ablocks, 256>>>(hs, x1, rowptr, adj, cb0, N);
    gemm_mma_kernel<1, 1><<<gblocks, 256, gemm_smem>>>(x1, W1, hs, N);
    agg_head_kernel<<<ablocks, 256>>>(hs, rowptr, adj, cb1, lW0, lb0, lW1, lb1, out, N);
}